// round 4
// baseline (speedup 1.0000x reference)
#include <cuda_runtime.h>

// DEC_LO (db4-ish lowpass) literals
#define D0 (-0.010597401784997278f)
#define D1 ( 0.032883011666982945f)
#define D2 ( 0.030841381835986965f)
#define D3 (-0.18703481171888114f)
#define D4 (-0.02798376941698385f)
#define D5 ( 0.6308807679295904f)
#define D6 ( 0.7148465705525415f)
#define D7 ( 0.23037781330885523f)

namespace {
constexpr int NT     = 512;      // threads per CTA
constexpr int ROWLEN = 32768;

// level lengths (derived exactly from reference padding math)
// lo1: 16387 (never materialized — folded into composite filter)
constexpr int L2N = 8197;
constexpr int L3N = 4102;
constexpr int L4N = 2054;

constexpr int HALO  = 8;
constexpr int BCAP  = 8198;      // max content per buffer (t2 = 8198)

// Two ping-pong buffers, each with 8-float zeroed halos on both sides.
// Data starts at even float offsets -> aligned float2 access everywhere.
constexpr int A_OFF = HALO;                        // 8
constexpr int B_OFF = A_OFF + BCAP + HALO + HALO;  // 8222 -> round to even: 8222 is even
constexpr int SMEM_FLOATS = B_OFF + BCAP + HALO;   // 16428
constexpr int SMEM_BYTES  = SMEM_FLOATS * (int)sizeof(float); // 65712 B -> 3 CTAs/SM

// h[s] = DEC_LO[7-s] (analysis filter, reversed)
__host__ __device__ constexpr float Hc(int s) {
    return (s == 0) ? D7 : (s == 1) ? D6 : (s == 2) ? D5 : (s == 3) ? D4
         : (s == 4) ? D3 : (s == 5) ? D2 : (s == 6) ? D1 : D0;
}
// Composite 22-tap filter: c[u] = sum_s h[s] * h[u-2s], 0 <= u-2s <= 7.
// lo2[j] = sum_u c[u] * x[4j + u - 18]  (exact composition; boundary indicator
// is automatic because out-of-range lo1 windows map entirely out of x's range)
__host__ __device__ constexpr float Cc(int u) {
    float acc = 0.f;
    for (int s = 0; s < 8; ++s) {
        int k = u - 2 * s;
        if (k >= 0 && k < 8) acc += Hc(s) * Hc(k);
    }
    return acc;
}
}

// Analysis step entirely in smem. `in` has 8 zeroed floats of halo each side;
// zeroes the upper halo of `out` for the next stage (also covers the
// reference's odd-p "append one zero" at levels 3/4).
// out[j] = sum_t h[t] * in[2j + t - 6]
__device__ __forceinline__ void afb_smem(const float* __restrict__ in, int N,
                                         float* __restrict__ out)
{
    const float h[8] = {D7, D6, D5, D4, D3, D2, D1, D0};
    const int outN = (N + 7) >> 1;
    for (int j = threadIdx.x; j < outN; j += NT) {
        const float2* p2 = reinterpret_cast<const float2*>(in + 2 * j - 6);
        float s = 0.f;
#pragma unroll
        for (int q = 0; q < 4; ++q) {
            float2 v = p2[q];
            s = fmaf(h[2 * q],     v.x, s);
            s = fmaf(h[2 * q + 1], v.y, s);
        }
        out[j] = s;
    }
    if (threadIdx.x < HALO) out[outN + threadIdx.x] = 0.f;
}

// Synthesis (transposed conv, lhs_dilation=2, pad 1) entirely in smem.
// out[2i]   = D1*in[i] + D3*in[i+1] + D5*in[i+2] + D7*in[i+3]
// out[2i+1] = D0*in[i] + D2*in[i+1] + D4*in[i+2] + D6*in[i+3],  i in [0, M-4]
__device__ __forceinline__ void sfb_smem(const float* __restrict__ in, int M,
                                         float* __restrict__ out)
{
    const int n = M - 3;
    float2* o2 = reinterpret_cast<float2*>(out);
    for (int i = threadIdx.x; i < n; i += NT) {
        float a = in[i], b = in[i + 1], c = in[i + 2], d = in[i + 3];
        float e = fmaf(D1, a, fmaf(D3, b, fmaf(D5, c, D7 * d)));
        float o = fmaf(D0, a, fmaf(D2, b, fmaf(D4, c, D6 * d)));
        o2[i] = make_float2(e, o);
    }
}

__global__ __launch_bounds__(NT, 3)
void WT_series_decomp_kernel(const float* __restrict__ x,
                             float* __restrict__ season,
                             float* __restrict__ trend)
{
    extern __shared__ float smem[];
    float* A = smem + A_OFF;
    float* B = smem + B_OFF;
    const int tid = threadIdx.x;
    const float* xr = x + (size_t)blockIdx.x * ROWLEN;

    // zero the (never-rewritten) lower halos once
    if (tid < HALO) { A[tid - HALO] = 0.f; B[tid - HALO] = 0.f; }

    // ---- Fused analysis levels 1+2: global x -> lo2 in A (L2N = 8197) ----
    {
        const float2* x2 = reinterpret_cast<const float2*>(xr);
        for (int j = tid; j < L2N; j += NT) {
            float s = 0.f;
            if (j >= 5 && j <= 8191) {
                // interior: x window [4j-18, 4j+3] = 11 aligned float2s
                const float2* p2 = x2 + (2 * j - 9);
#pragma unroll
                for (int q = 0; q < 11; ++q) {
                    float2 v = __ldg(&p2[q]);
                    s = fmaf(Cc(2 * q),     v.x, s);
                    s = fmaf(Cc(2 * q + 1), v.y, s);
                }
            } else {
#pragma unroll
                for (int u = 0; u < 22; ++u) {
                    int idx = 4 * j + u - 18;
                    float v = ((unsigned)idx < (unsigned)ROWLEN) ? xr[idx] : 0.f;
                    s = fmaf(Cc(u), v, s);
                }
            }
            A[j] = s;
        }
        if (tid < HALO) A[L2N + tid] = 0.f;
    }
    __syncthreads();

    afb_smem(A, L2N, B);  __syncthreads();   // lo3: 4102 in B
    afb_smem(B, L3N, A);  __syncthreads();   // lo4: 2054 in A (overwrites lo2)

    sfb_smem(A, L4N, B);  __syncthreads();   // t1: 4102 in B (overwrites lo3)
    sfb_smem(B, L3N, A);  __syncthreads();   // t2: 8198 in A (use first 8197)

    // ---- Fused final two synthesis stages (t2 -> t3 -> out, t3 in registers)
    //      + season = x - trend, streamed to global as float4 ----
    {
        const float4* x4  = reinterpret_cast<const float4*>(xr);
        float4* tr4 = reinterpret_cast<float4*>(trend  + (size_t)blockIdx.x * ROWLEN);
        float4* se4 = reinterpret_cast<float4*>(season + (size_t)blockIdx.x * ROWLEN);
        const float* T = A;  // t2
        for (int i = tid; i < ROWLEN / 4; i += NT) {
            float a0 = T[i],     a1 = T[i + 1], a2 = T[i + 2];
            float a3 = T[i + 3], a4 = T[i + 4], a5 = T[i + 5];
            // t3[2i..2i+4] on the fly
            float e0 = fmaf(D1, a0, fmaf(D3, a1, fmaf(D5, a2, D7 * a3)));  // t3[2i]
            float o0 = fmaf(D0, a0, fmaf(D2, a1, fmaf(D4, a2, D6 * a3)));  // t3[2i+1]
            float e1 = fmaf(D1, a1, fmaf(D3, a2, fmaf(D5, a3, D7 * a4)));  // t3[2i+2]
            float o1 = fmaf(D0, a1, fmaf(D2, a2, fmaf(D4, a3, D6 * a4)));  // t3[2i+3]
            float e2 = fmaf(D1, a2, fmaf(D3, a3, fmaf(D5, a4, D7 * a5)));  // t3[2i+4]
            // final synthesis from t3
            float y0 = fmaf(D1, e0, fmaf(D3, o0, fmaf(D5, e1, D7 * o1)));  // out[4i]
            float y1 = fmaf(D0, e0, fmaf(D2, o0, fmaf(D4, e1, D6 * o1)));  // out[4i+1]
            float y2 = fmaf(D1, o0, fmaf(D3, e1, fmaf(D5, o1, D7 * e2)));  // out[4i+2]
            float y3 = fmaf(D0, o0, fmaf(D2, e1, fmaf(D4, o1, D6 * e2)));  // out[4i+3]
            float4 xv = __ldg(&x4[i]);
            tr4[i] = make_float4(y0, y1, y2, y3);
            se4[i] = make_float4(xv.x - y0, xv.y - y1, xv.z - y2, xv.w - y3);
        }
    }
}

extern "C" void kernel_launch(void* const* d_in, const int* in_sizes, int n_in,
                              void* d_out, int out_size)
{
    const float* x = (const float*)d_in[0];
    const int rows = in_sizes[0] / ROWLEN;   // 32 * 16 = 512 for this shape
    float* out = (float*)d_out;
    float* season = out;                                  // tuple element 0
    float* trend  = out + (size_t)rows * ROWLEN;          // tuple element 1

    cudaFuncSetAttribute(WT_series_decomp_kernel,
                         cudaFuncAttributeMaxDynamicSharedMemorySize, SMEM_BYTES);
    WT_series_decomp_kernel<<<rows, NT, SMEM_BYTES>>>(x, season, trend);
}